// round 2
// baseline (speedup 1.0000x reference)
#include <cuda_runtime.h>
#include <cuda_bf16.h>
#include <math.h>

// Problem constants (from reference setup_inputs)
#define S_TOK 4096      // B*s = 4*1024
#define DIM   1024      // D
#define NEXP  8         // E
#define HID   4096      // H
#define NSCORES (NEXP * S_TOK)  // 32768

// ---------------- device scratch (no allocations allowed) ----------------
__device__ float g_scores[NSCORES];          // [E][S] softmax scores
__device__ float g_thresh;                   // k-th largest score (exact)
__device__ int   g_cnt[NEXP];                // tokens routed per expert
__device__ int   g_rows[NEXP * S_TOK];       // token id per routed row
__device__ float g_w[NEXP * S_TOK];          // gate weight per routed row
__device__ int   g_pos[NSCORES];             // [e*S+s] -> row in expert list, or -1
__device__ float g_hidden[(size_t)NEXP * S_TOK * HID];   // 536 MB: gelu(X@W1+b1)
__device__ float g_y[(size_t)NEXP * S_TOK * DIM];        // 134 MB: w*(H@W2+b2)

// ---------------- init ----------------
__global__ void zero_cnt_kernel() {
    if (threadIdx.x < NEXP) g_cnt[threadIdx.x] = 0;
}

// ---------------- router: logits + softmax over experts ----------------
// one block (256 thr = 8 warps) per token; warp e computes dot(gate_w[e], x[s])
__global__ void router_kernel(const float* __restrict__ x,
                              const float* __restrict__ gw,
                              const float* __restrict__ eb) {
    int s = blockIdx.x;
    int warp = threadIdx.x >> 5, lane = threadIdx.x & 31;
    const float* xs = x + (size_t)s * DIM;
    const float* g  = gw + (size_t)warp * DIM;
    float acc = 0.f;
    for (int i = lane; i < DIM; i += 32) acc += xs[i] * g[i];
    #pragma unroll
    for (int o = 16; o; o >>= 1) acc += __shfl_xor_sync(0xFFFFFFFFu, acc, o);
    __shared__ float l[NEXP];
    if (lane == 0) l[warp] = acc + eb[warp];
    __syncthreads();
    if (threadIdx.x < NEXP) {
        float m = l[0];
        #pragma unroll
        for (int e = 1; e < NEXP; e++) m = fmaxf(m, l[e]);
        float sum = 0.f;
        #pragma unroll
        for (int e = 0; e < NEXP; e++) sum += expf(l[e] - m);
        g_scores[threadIdx.x * S_TOK + s] = expf(l[threadIdx.x] - m) / sum;
    }
}

// ---------------- exact global top-k threshold via 4-round radix select ----
// scores are softmax outputs (>0), so positive-float bits order == float order
__global__ void topk_kernel(const int* __restrict__ cap) {
    __shared__ int hist[256];
    __shared__ unsigned sh_prefix;
    __shared__ int sh_k;
    int k = S_TOK * cap[0];           // k = S * capacity
    if (k < 1) k = 1;
    if (k > NSCORES) k = NSCORES;
    unsigned prefix = 0, mask = 0;
    int kk = k;
    for (int shift = 24; shift >= 0; shift -= 8) {
        for (int i = threadIdx.x; i < 256; i += blockDim.x) hist[i] = 0;
        __syncthreads();
        for (int i = threadIdx.x; i < NSCORES; i += blockDim.x) {
            unsigned u = __float_as_uint(g_scores[i]);
            if ((u & mask) == prefix) atomicAdd(&hist[(u >> shift) & 255], 1);
        }
        __syncthreads();
        if (threadIdx.x == 0) {
            int rem = kk, b = 255;
            for (; b >= 0; --b) {
                if (rem <= hist[b]) break;
                rem -= hist[b];
            }
            if (b < 0) b = 0;
            sh_prefix = prefix | ((unsigned)b << shift);
            sh_k = rem;
        }
        __syncthreads();
        prefix = sh_prefix;
        kk = sh_k;
        mask |= (0xFFu << shift);
        __syncthreads();
    }
    if (threadIdx.x == 0) g_thresh = __uint_as_float(prefix);
}

// ---------------- build per-expert routed lists ----------------
__global__ void build_kernel() {
    int i = blockIdx.x * blockDim.x + threadIdx.x;   // 0..NSCORES-1
    if (i >= NSCORES) return;
    float sc = g_scores[i];
    int e = i >> 12;          // /S_TOK
    int p = -1;
    if (sc >= g_thresh) {
        int r = atomicAdd(&g_cnt[e], 1);
        g_rows[e * S_TOK + r] = i & (S_TOK - 1);
        g_w[e * S_TOK + r]    = sc;
        p = r;
    }
    g_pos[i] = p;
}

// ---------------- GEMM tiling ----------------
#define BM 64
#define BN 128
#define BK 16
// 256 threads, thread tile 4x8

// GEMM1: H[e][row][h] = gelu( x[tok[row]] @ w1[e] + b1[e] )
__global__ __launch_bounds__(256)
void gemm1_kernel(const float* __restrict__ x,
                  const float* __restrict__ w1,
                  const float* __restrict__ b1) {
    int e = blockIdx.z;
    int n = g_cnt[e];
    int row0 = blockIdx.x * BM;
    if (row0 >= n) return;
    int col0 = blockIdx.y * BN;
    const float* B = w1 + (size_t)e * DIM * HID;

    __shared__ float As[BK][BM];
    __shared__ float Bs[BK][BN];
    __shared__ int toks[BM];

    int tid = threadIdx.x;
    if (tid < BM) {
        int mg = row0 + tid;
        if (mg >= n) mg = n - 1;
        toks[tid] = g_rows[e * S_TOK + mg];
    }
    __syncthreads();

    float acc[4][8];
    #pragma unroll
    for (int i = 0; i < 4; i++)
        #pragma unroll
        for (int j = 0; j < 8; j++) acc[i][j] = 0.f;

    int ty = tid >> 4, tx = tid & 15;
    int am = tid >> 2, ak = (tid & 3) * 4;

    for (int k0 = 0; k0 < DIM; k0 += BK) {
        // A tile: 64x16 = 256 float4 (1/thread), transpose into As[k][m]
        float4 av = *(const float4*)(x + (size_t)toks[am] * DIM + k0 + ak);
        As[ak + 0][am] = av.x; As[ak + 1][am] = av.y;
        As[ak + 2][am] = av.z; As[ak + 3][am] = av.w;
        // B tile: 16x128 = 512 float4 (2/thread)
        #pragma unroll
        for (int i = 0; i < 2; i++) {
            int t  = tid + i * 256;
            int bk = t >> 5;
            int bn = (t & 31) * 4;
            *(float4*)&Bs[bk][bn] = *(const float4*)(B + (size_t)(k0 + bk) * HID + col0 + bn);
        }
        __syncthreads();
        #pragma unroll
        for (int kk = 0; kk < BK; kk++) {
            float a[4], b[8];
            *(float4*)a      = *(float4*)&As[kk][ty * 4];
            *(float4*)&b[0]  = *(float4*)&Bs[kk][tx * 8];
            *(float4*)&b[4]  = *(float4*)&Bs[kk][tx * 8 + 4];
            #pragma unroll
            for (int i = 0; i < 4; i++)
                #pragma unroll
                for (int j = 0; j < 8; j++)
                    acc[i][j] = fmaf(a[i], b[j], acc[i][j]);
        }
        __syncthreads();
    }

    const float* b1e = b1 + (size_t)e * HID;
    float* Hrow = g_hidden + (size_t)e * S_TOK * HID;
    #pragma unroll
    for (int i = 0; i < 4; i++) {
        int r = row0 + ty * 4 + i;
        if (r >= n) continue;
        #pragma unroll
        for (int j = 0; j < 8; j++) {
            int c = col0 + tx * 8 + j;
            float v = acc[i][j] + b1e[c];
            float t = tanhf(0.7978845608028654f * (v + 0.044715f * v * v * v));
            Hrow[(size_t)r * HID + c] = 0.5f * v * (1.0f + t);
        }
    }
}

// GEMM2: y[e][row][d] = w[row] * ( H[e][row] @ w2[e] + b2[e] )
__global__ __launch_bounds__(256)
void gemm2_kernel(const float* __restrict__ w2,
                  const float* __restrict__ b2) {
    int e = blockIdx.z;
    int n = g_cnt[e];
    int row0 = blockIdx.x * BM;
    if (row0 >= n) return;
    int col0 = blockIdx.y * BN;
    const float* A = g_hidden + (size_t)e * S_TOK * HID;
    const float* B = w2 + (size_t)e * HID * DIM;

    __shared__ float As[BK][BM];
    __shared__ float Bs[BK][BN];

    int tid = threadIdx.x;
    int ty = tid >> 4, tx = tid & 15;
    int am = tid >> 2, ak = (tid & 3) * 4;
    int mg = row0 + am;
    if (mg >= n) mg = n - 1;

    float acc[4][8];
    #pragma unroll
    for (int i = 0; i < 4; i++)
        #pragma unroll
        for (int j = 0; j < 8; j++) acc[i][j] = 0.f;

    for (int k0 = 0; k0 < HID; k0 += BK) {
        float4 av = *(const float4*)(A + (size_t)mg * HID + k0 + ak);
        As[ak + 0][am] = av.x; As[ak + 1][am] = av.y;
        As[ak + 2][am] = av.z; As[ak + 3][am] = av.w;
        #pragma unroll
        for (int i = 0; i < 2; i++) {
            int t  = tid + i * 256;
            int bk = t >> 5;
            int bn = (t & 31) * 4;
            *(float4*)&Bs[bk][bn] = *(const float4*)(B + (size_t)(k0 + bk) * DIM + col0 + bn);
        }
        __syncthreads();
        #pragma unroll
        for (int kk = 0; kk < BK; kk++) {
            float a[4], b[8];
            *(float4*)a      = *(float4*)&As[kk][ty * 4];
            *(float4*)&b[0]  = *(float4*)&Bs[kk][tx * 8];
            *(float4*)&b[4]  = *(float4*)&Bs[kk][tx * 8 + 4];
            #pragma unroll
            for (int i = 0; i < 4; i++)
                #pragma unroll
                for (int j = 0; j < 8; j++)
                    acc[i][j] = fmaf(a[i], b[j], acc[i][j]);
        }
        __syncthreads();
    }

    const float* b2e = b2 + (size_t)e * DIM;
    #pragma unroll
    for (int i = 0; i < 4; i++) {
        int r = row0 + ty * 4 + i;
        if (r >= n) continue;
        float wg = g_w[e * S_TOK + r];
        #pragma unroll
        for (int j = 0; j < 8; j++) {
            int c = col0 + tx * 8 + j;
            g_y[((size_t)e * S_TOK + r) * DIM + c] = wg * (acc[i][j] + b2e[c]);
        }
    }
}

// ---------------- deterministic combine (no atomics) ----------------
__global__ void combine_kernel(float* __restrict__ out) {
    int s = blockIdx.y;
    int d = blockIdx.x * blockDim.x + threadIdx.x;
    float acc = 0.f;
    #pragma unroll
    for (int e = 0; e < NEXP; e++) {
        int p = g_pos[e * S_TOK + s];
        if (p >= 0) acc += g_y[((size_t)e * S_TOK + p) * DIM + d];
    }
    out[(size_t)s * DIM + d] = acc;
}

// ---------------- launch ----------------
extern "C" void kernel_launch(void* const* d_in, const int* in_sizes, int n_in,
                              void* d_out, int out_size) {
    const float* x  = (const float*)d_in[0];
    const float* gw = (const float*)d_in[1];
    const float* eb = (const float*)d_in[2];
    const float* w1 = (const float*)d_in[3];
    const float* b1 = (const float*)d_in[4];
    const float* w2 = (const float*)d_in[5];
    const float* b2 = (const float*)d_in[6];
    const int*  cap = (const int*)d_in[7];
    float* out = (float*)d_out;

    zero_cnt_kernel<<<1, 32>>>();
    router_kernel<<<S_TOK, 256>>>(x, gw, eb);
    topk_kernel<<<1, 256>>>(cap);
    build_kernel<<<NSCORES / 256, 256>>>();
    gemm1_kernel<<<dim3(S_TOK / BM, HID / BN, NEXP), 256>>>(x, w1, b1);
    gemm2_kernel<<<dim3(S_TOK / BM, DIM / BN, NEXP), 256>>>(w2, b2);
    combine_kernel<<<dim3(DIM / 256, S_TOK), 256>>>(out);
}

// round 3
// speedup vs baseline: 4.0561x; 4.0561x over previous
#include <cuda_runtime.h>
#include <cuda_bf16.h>
#include <math.h>

// Problem constants (from reference setup_inputs)
#define S_TOK 4096      // B*s
#define DIM   1024      // D
#define NEXP  8         // E
#define HID   4096      // H
#define NSCORES (NEXP * S_TOK)  // 32768

// ---------------- device scratch ----------------
__device__ float g_scores[NSCORES];
__device__ float g_thresh;
__device__ int   g_cnt[NEXP];
__device__ int   g_rows[NEXP * S_TOK];
__device__ float g_w[NEXP * S_TOK];
__device__ int   g_pos[NSCORES];
__device__ float g_hidden[(size_t)NEXP * S_TOK * HID];
__device__ float g_y[(size_t)NEXP * S_TOK * DIM];

__global__ void zero_cnt_kernel() {
    if (threadIdx.x < NEXP) g_cnt[threadIdx.x] = 0;
}

// ---------------- router (exact fp32) ----------------
__global__ void router_kernel(const float* __restrict__ x,
                              const float* __restrict__ gw,
                              const float* __restrict__ eb) {
    int s = blockIdx.x;
    int warp = threadIdx.x >> 5, lane = threadIdx.x & 31;
    const float* xs = x + (size_t)s * DIM;
    const float* g  = gw + (size_t)warp * DIM;
    float acc = 0.f;
    for (int i = lane; i < DIM; i += 32) acc += xs[i] * g[i];
    #pragma unroll
    for (int o = 16; o; o >>= 1) acc += __shfl_xor_sync(0xFFFFFFFFu, acc, o);
    __shared__ float l[NEXP];
    if (lane == 0) l[warp] = acc + eb[warp];
    __syncthreads();
    if (threadIdx.x < NEXP) {
        float m = l[0];
        #pragma unroll
        for (int e = 1; e < NEXP; e++) m = fmaxf(m, l[e]);
        float sum = 0.f;
        #pragma unroll
        for (int e = 0; e < NEXP; e++) sum += expf(l[e] - m);
        g_scores[threadIdx.x * S_TOK + s] = expf(l[threadIdx.x] - m) / sum;
    }
}

// ---------------- exact global top-k threshold (radix select) ----------------
__global__ void topk_kernel(const int* __restrict__ cap) {
    __shared__ int hist[256];
    __shared__ unsigned sh_prefix;
    __shared__ int sh_k;
    int k = S_TOK * cap[0];
    if (k < 1) k = 1;
    if (k > NSCORES) k = NSCORES;
    unsigned prefix = 0, mask = 0;
    int kk = k;
    for (int shift = 24; shift >= 0; shift -= 8) {
        for (int i = threadIdx.x; i < 256; i += blockDim.x) hist[i] = 0;
        __syncthreads();
        for (int i = threadIdx.x; i < NSCORES; i += blockDim.x) {
            unsigned u = __float_as_uint(g_scores[i]);
            if ((u & mask) == prefix) atomicAdd(&hist[(u >> shift) & 255], 1);
        }
        __syncthreads();
        if (threadIdx.x == 0) {
            int rem = kk, b = 255;
            for (; b >= 0; --b) {
                if (rem <= hist[b]) break;
                rem -= hist[b];
            }
            if (b < 0) b = 0;
            sh_prefix = prefix | ((unsigned)b << shift);
            sh_k = rem;
        }
        __syncthreads();
        prefix = sh_prefix;
        kk = sh_k;
        mask |= (0xFFu << shift);
        __syncthreads();
    }
    if (threadIdx.x == 0) g_thresh = __uint_as_float(prefix);
}

__global__ void build_kernel() {
    int i = blockIdx.x * blockDim.x + threadIdx.x;
    if (i >= NSCORES) return;
    float sc = g_scores[i];
    int e = i >> 12;
    int p = -1;
    if (sc >= g_thresh) {
        int r = atomicAdd(&g_cnt[e], 1);
        g_rows[e * S_TOK + r] = i & (S_TOK - 1);
        g_w[e * S_TOK + r]    = sc;
        p = r;
    }
    g_pos[i] = p;
}

// ---------------- tf32 tensor-core GEMM ----------------
#define BM 128
#define BN 128
#define BK 16
#define ASTR 20      // As row stride (floats): banks (20*gid+tig)%32 all distinct
#define BSTR 136     // Bs row stride: banks (8*tig+gid)%32 all distinct

__device__ __forceinline__ unsigned f2tf(float f) {
    unsigned u;
    asm("cvt.rna.tf32.f32 %0, %1;" : "=r"(u) : "f"(f));
    return u;
}
__device__ __forceinline__ uint4 cvt4(float4 v) {
    uint4 r;
    r.x = f2tf(v.x); r.y = f2tf(v.y); r.z = f2tf(v.z); r.w = f2tf(v.w);
    return r;
}
__device__ __forceinline__ void mma_tf32(float* c, const unsigned* a, const unsigned* b) {
    asm volatile("mma.sync.aligned.m16n8k8.row.col.f32.tf32.tf32.f32 "
        "{%0,%1,%2,%3}, {%4,%5,%6,%7}, {%8,%9}, {%0,%1,%2,%3};"
        : "+f"(c[0]), "+f"(c[1]), "+f"(c[2]), "+f"(c[3])
        : "r"(a[0]), "r"(a[1]), "r"(a[2]), "r"(a[3]), "r"(b[0]), "r"(b[1]));
}

// GEMM1: g_hidden[e][r][h] = gelu( x[tok[r]] @ w1[e] + b1[e] ),  K=DIM
__global__ __launch_bounds__(256, 2)
void gemm1_kernel(const float* __restrict__ x,
                  const float* __restrict__ w1,
                  const float* __restrict__ b1) {
    int e = blockIdx.z;
    int n = g_cnt[e];
    int row0 = blockIdx.x * BM;
    if (row0 >= n) return;
    int col0 = blockIdx.y * BN;
    const float* Bg = w1 + (size_t)e * DIM * HID;
    const int ldb = HID;
    const int K = DIM;

    __shared__ __align__(16) unsigned As[BM][ASTR];
    __shared__ __align__(16) unsigned Bs[BK][BSTR];
    __shared__ int toks[BM];

    int tid = threadIdx.x;
    if (tid < BM) {
        int mg = row0 + tid;
        if (mg >= n) mg = n - 1;
        toks[tid] = g_rows[e * S_TOK + mg];
    }
    __syncthreads();

    int lane = tid & 31;
    int warp = tid >> 5;
    int gid = lane >> 2, tig = lane & 3;
    int wm = (warp & 1) * 64, wn = (warp >> 1) * 32;

    float acc[4][4][4];
    #pragma unroll
    for (int mt = 0; mt < 4; mt++)
        #pragma unroll
        for (int nt = 0; nt < 4; nt++)
            #pragma unroll
            for (int i = 0; i < 4; i++) acc[mt][nt][i] = 0.f;

    // staging assignments: A tile 128x16 = 512 float4, B tile 16x128 = 512 float4
    int aRow0 = tid >> 2,        aK = (tid & 3) * 4;
    int aRow1 = aRow0 + 64;
    int bK0 = tid >> 5,          bN = lane * 4;       // rows 0..7 and 8..15

    const float* aPtr0 = x + (size_t)toks[aRow0] * DIM + aK;
    const float* aPtr1 = x + (size_t)toks[aRow1] * DIM + aK;
    const float* bPtr0 = Bg + (size_t)bK0 * ldb + col0 + bN;
    const float* bPtr1 = Bg + (size_t)(bK0 + 8) * ldb + col0 + bN;

    float4 ra0 = *(const float4*)aPtr0;
    float4 ra1 = *(const float4*)aPtr1;
    float4 rb0 = *(const float4*)bPtr0;
    float4 rb1 = *(const float4*)bPtr1;

    for (int k0 = 0;;) {
        *(uint4*)&As[aRow0][aK]  = cvt4(ra0);
        *(uint4*)&As[aRow1][aK]  = cvt4(ra1);
        *(uint4*)&Bs[bK0][bN]    = cvt4(rb0);
        *(uint4*)&Bs[bK0 + 8][bN] = cvt4(rb1);
        __syncthreads();

        k0 += BK;
        bool more = (k0 < K);
        if (more) {
            ra0 = *(const float4*)(aPtr0 + k0);
            ra1 = *(const float4*)(aPtr1 + k0);
            rb0 = *(const float4*)(bPtr0 + (size_t)k0 * ldb);
            rb1 = *(const float4*)(bPtr1 + (size_t)k0 * ldb);
        }

        #pragma unroll
        for (int ks = 0; ks < 2; ks++) {
            unsigned af[4][4], bf[4][2];
            #pragma unroll
            for (int mt = 0; mt < 4; mt++) {
                int r = wm + mt * 16 + gid;
                af[mt][0] = As[r][ks * 8 + tig];
                af[mt][1] = As[r + 8][ks * 8 + tig];
                af[mt][2] = As[r][ks * 8 + tig + 4];
                af[mt][3] = As[r + 8][ks * 8 + tig + 4];
            }
            #pragma unroll
            for (int nt = 0; nt < 4; nt++) {
                bf[nt][0] = Bs[ks * 8 + tig][wn + nt * 8 + gid];
                bf[nt][1] = Bs[ks * 8 + tig + 4][wn + nt * 8 + gid];
            }
            #pragma unroll
            for (int mt = 0; mt < 4; mt++)
                #pragma unroll
                for (int nt = 0; nt < 4; nt++)
                    mma_tf32(acc[mt][nt], af[mt], bf[nt]);
        }
        if (!more) break;
        __syncthreads();
    }

    const float* b1e = b1 + (size_t)e * HID;
    float* Hb = g_hidden + (size_t)e * S_TOK * HID;
    #pragma unroll
    for (int mt = 0; mt < 4; mt++) {
        #pragma unroll
        for (int half = 0; half < 2; half++) {
            int r = row0 + wm + mt * 16 + gid + half * 8;
            if (r >= n) continue;
            #pragma unroll
            for (int nt = 0; nt < 4; nt++) {
                int c = col0 + wn + nt * 8 + 2 * tig;
                float v0 = acc[mt][nt][half * 2 + 0] + b1e[c];
                float v1 = acc[mt][nt][half * 2 + 1] + b1e[c + 1];
                float t0 = tanhf(0.7978845608028654f * (v0 + 0.044715f * v0 * v0 * v0));
                float t1 = tanhf(0.7978845608028654f * (v1 + 0.044715f * v1 * v1 * v1));
                float2 o;
                o.x = 0.5f * v0 * (1.0f + t0);
                o.y = 0.5f * v1 * (1.0f + t1);
                *(float2*)&Hb[(size_t)r * HID + c] = o;
            }
        }
    }
}

// GEMM2: g_y[e][r][d] = g_w[r] * ( g_hidden[e][r] @ w2[e] + b2[e] ),  K=HID
__global__ __launch_bounds__(256, 2)
void gemm2_kernel(const float* __restrict__ w2,
                  const float* __restrict__ b2) {
    int e = blockIdx.z;
    int n = g_cnt[e];
    int row0 = blockIdx.x * BM;
    if (row0 >= n) return;
    int col0 = blockIdx.y * BN;
    const float* Ag = g_hidden + (size_t)e * S_TOK * HID;
    const float* Bg = w2 + (size_t)e * HID * DIM;
    const int ldb = DIM;
    const int K = HID;

    __shared__ __align__(16) unsigned As[BM][ASTR];
    __shared__ __align__(16) unsigned Bs[BK][BSTR];

    int tid = threadIdx.x;
    int lane = tid & 31;
    int warp = tid >> 5;
    int gid = lane >> 2, tig = lane & 3;
    int wm = (warp & 1) * 64, wn = (warp >> 1) * 32;

    float acc[4][4][4];
    #pragma unroll
    for (int mt = 0; mt < 4; mt++)
        #pragma unroll
        for (int nt = 0; nt < 4; nt++)
            #pragma unroll
            for (int i = 0; i < 4; i++) acc[mt][nt][i] = 0.f;

    int aRow0 = tid >> 2,        aK = (tid & 3) * 4;
    int aRow1 = aRow0 + 64;
    int bK0 = tid >> 5,          bN = lane * 4;
    int mg0 = row0 + aRow0; if (mg0 >= n) mg0 = n - 1;
    int mg1 = row0 + aRow1; if (mg1 >= n) mg1 = n - 1;

    const float* aPtr0 = Ag + (size_t)mg0 * HID + aK;
    const float* aPtr1 = Ag + (size_t)mg1 * HID + aK;
    const float* bPtr0 = Bg + (size_t)bK0 * ldb + col0 + bN;
    const float* bPtr1 = Bg + (size_t)(bK0 + 8) * ldb + col0 + bN;

    float4 ra0 = *(const float4*)aPtr0;
    float4 ra1 = *(const float4*)aPtr1;
    float4 rb0 = *(const float4*)bPtr0;
    float4 rb1 = *(const float4*)bPtr1;

    for (int k0 = 0;;) {
        *(uint4*)&As[aRow0][aK]  = cvt4(ra0);
        *(uint4*)&As[aRow1][aK]  = cvt4(ra1);
        *(uint4*)&Bs[bK0][bN]    = cvt4(rb0);
        *(uint4*)&Bs[bK0 + 8][bN] = cvt4(rb1);
        __syncthreads();

        k0 += BK;
        bool more = (k0 < K);
        if (more) {
            ra0 = *(const float4*)(aPtr0 + k0);
            ra1 = *(const float4*)(aPtr1 + k0);
            rb0 = *(const float4*)(bPtr0 + (size_t)k0 * ldb);
            rb1 = *(const float4*)(bPtr1 + (size_t)k0 * ldb);
        }

        #pragma unroll
        for (int ks = 0; ks < 2; ks++) {
            unsigned af[4][4], bf[4][2];
            #pragma unroll
            for (int mt = 0; mt < 4; mt++) {
                int r = wm + mt * 16 + gid;
                af[mt][0] = As[r][ks * 8 + tig];
                af[mt][1] = As[r + 8][ks * 8 + tig];
                af[mt][2] = As[r][ks * 8 + tig + 4];
                af[mt][3] = As[r + 8][ks * 8 + tig + 4];
            }
            #pragma unroll
            for (int nt = 0; nt < 4; nt++) {
                bf[nt][0] = Bs[ks * 8 + tig][wn + nt * 8 + gid];
                bf[nt][1] = Bs[ks * 8 + tig + 4][wn + nt * 8 + gid];
            }
            #pragma unroll
            for (int mt = 0; mt < 4; mt++)
                #pragma unroll
                for (int nt = 0; nt < 4; nt++)
                    mma_tf32(acc[mt][nt], af[mt], bf[nt]);
        }
        if (!more) break;
        __syncthreads();
    }

    const float* b2e = b2 + (size_t)e * DIM;
    #pragma unroll
    for (int mt = 0; mt < 4; mt++) {
        #pragma unroll
        for (int half = 0; half < 2; half++) {
            int r = row0 + wm + mt * 16 + gid + half * 8;
            if (r >= n) continue;
            float wg = g_w[e * S_TOK + r];
            #pragma unroll
            for (int nt = 0; nt < 4; nt++) {
                int c = col0 + wn + nt * 8 + 2 * tig;
                float2 o;
                o.x = wg * (acc[mt][nt][half * 2 + 0] + b2e[c]);
                o.y = wg * (acc[mt][nt][half * 2 + 1] + b2e[c + 1]);
                *(float2*)&g_y[((size_t)e * S_TOK + r) * DIM + c] = o;
            }
        }
    }
}

// ---------------- deterministic combine ----------------
__global__ void combine_kernel(float* __restrict__ out) {
    int s = blockIdx.y;
    int d = blockIdx.x * blockDim.x + threadIdx.x;
    float acc = 0.f;
    #pragma unroll
    for (int e = 0; e < NEXP; e++) {
        int p = g_pos[e * S_TOK + s];
        if (p >= 0) acc += g_y[((size_t)e * S_TOK + p) * DIM + d];
    }
    out[(size_t)s * DIM + d] = acc;
}

// ---------------- launch ----------------
extern "C" void kernel_launch(void* const* d_in, const int* in_sizes, int n_in,
                              void* d_out, int out_size) {
    const float* x  = (const float*)d_in[0];
    const float* gw = (const float*)d_in[1];
    const float* eb = (const float*)d_in[2];
    const float* w1 = (const float*)d_in[3];
    const float* b1 = (const float*)d_in[4];
    const float* w2 = (const float*)d_in[5];
    const float* b2 = (const float*)d_in[6];
    const int*  cap = (const int*)d_in[7];
    float* out = (float*)d_out;

    zero_cnt_kernel<<<1, 32>>>();
    router_kernel<<<S_TOK, 256>>>(x, gw, eb);
    topk_kernel<<<1, 256>>>(cap);
    build_kernel<<<NSCORES / 256, 256>>>();
    gemm1_kernel<<<dim3(S_TOK / BM, HID / BN, NEXP), 256>>>(x, w1, b1);
    gemm2_kernel<<<dim3(S_TOK / BM, DIM / BN, NEXP), 256>>>(w2, b2);
    combine_kernel<<<dim3(DIM / 256, S_TOK), 256>>>(out);
}